// round 1
// baseline (speedup 1.0000x reference)
#include <cuda_runtime.h>
#include <cstdint>

#define RDIM 64
#define ODIM 256
#define IDIM 256
#define ENT  64

typedef unsigned long long u64;

__device__ float g_Wsum[RDIM * ODIM];     // 64 KB, L2-resident
__device__ float g_xsum[131072];          // E <= 131072

__device__ __forceinline__ float frcp_approx(float a) {
    float r; asm("rcp.approx.f32 %0, %1;" : "=f"(r) : "f"(a)); return r;
}
__device__ __forceinline__ u64 ffma2(u64 a, u64 b, u64 c) {
    u64 d; asm("fma.rn.f32x2 %0, %1, %2, %3;" : "=l"(d) : "l"(a), "l"(b), "l"(c)); return d;
}
__device__ __forceinline__ u64 fadd2(u64 a, u64 b) {
    u64 d; asm("add.rn.f32x2 %0, %1, %2;" : "=l"(d) : "l"(a), "l"(b)); return d;
}
__device__ __forceinline__ u64 fmul2(u64 a, u64 b) {
    u64 d; asm("mul.rn.f32x2 %0, %1, %2;" : "=l"(d) : "l"(a), "l"(b)); return d;
}
__device__ __forceinline__ u64 pack2(float lo, float hi) {
    u64 d; asm("mov.b64 %0, {%1, %2};" : "=l"(d) : "f"(lo), "f"(hi)); return d;
}

// ---------------------------------------------------------------------------
// Kernel 1: W_sum[r][o] = sum_i W[r][i][o].  64 blocks x 1024 threads,
// 4-way split over i with smem combine.
// ---------------------------------------------------------------------------
__global__ void wsum_kernel(const float* __restrict__ W) {
    __shared__ float s[4][ODIM];
    int r = blockIdx.x;
    int o = threadIdx.x & 255;
    int q = threadIdx.x >> 8;
    const float* p = W + (size_t)r * IDIM * ODIM + (size_t)q * (IDIM / 4) * ODIM + o;
    float acc = 0.f;
    #pragma unroll 8
    for (int i = 0; i < IDIM / 4; i++) acc += p[(size_t)i * ODIM];
    s[q][o] = acc;
    __syncthreads();
    if (q == 0) g_Wsum[r * ODIM + o] = (s[0][o] + s[1][o]) + (s[2][o] + s[3][o]);
}

// ---------------------------------------------------------------------------
// Kernel 2: x_sum[e] = sum_j x[e][j].  One warp per row, float4 loads.
// ---------------------------------------------------------------------------
__global__ void xsum_kernel(const float* __restrict__ x, int E) {
    int gwarp = (int)((blockIdx.x * (unsigned)blockDim.x + threadIdx.x) >> 5);
    int lane = threadIdx.x & 31;
    if (gwarp >= E) return;
    const float4* p = (const float4*)(x + (size_t)gwarp * IDIM);
    float4 a = p[lane];
    float4 b = p[lane + 32];
    float s = ((a.x + a.y) + (a.z + a.w)) + ((b.x + b.y) + (b.z + b.w));
    #pragma unroll
    for (int off = 16; off; off >>= 1) s += __shfl_xor_sync(0xffffffffu, s, off);
    if (lane == 0) g_xsum[gwarp] = s;
}

// ---------------------------------------------------------------------------
// Kernel 3: out[e][o] = x_sum[e] * sum_r rcp_cs[e][r] * Wsum[r][o]
// 128 threads/block; thread t owns packed output columns (2t, 2t+1).
// Wsum column pair lives in 64 x u64 registers (f32x2).
// rcp(cs) staged in smem PRE-DUPLICATED as (v,v) pairs so the inner loop is
// pure LDS.128(broadcast) + FFMA2: 32 LDS + 64 FFMA2 per entity per thread.
// ---------------------------------------------------------------------------
__global__ __launch_bounds__(128, 2) void rgcn_main_kernel(
        const float* __restrict__ cs, float* __restrict__ out, int E) {
    __shared__ float2 s_rcp[ENT][RDIM];   // 32 KB: duplicated reciprocal pairs
    __shared__ float  s_xs[ENT];
    int tid = threadIdx.x;
    int e0 = blockIdx.x * ENT;

    // Load this thread's Wsum column pair into registers (from L2-resident table)
    u64 w[RDIM];
    #pragma unroll
    for (int r = 0; r < RDIM; r++)
        w[r] = *(const u64*)(g_Wsum + r * ODIM + 2 * tid);

    // Stage: ENT*RDIM = 4096 floats of cs -> rcp -> duplicated float2 in smem
    const float4* csp = (const float4*)(cs + (size_t)e0 * RDIM);
    #pragma unroll
    for (int k = 0; k < 8; k++) {
        int idx = k * 128 + tid;          // float4 index within batch: 0..1023
        int e  = idx >> 4;                // 16 float4 per entity row
        int r4 = (idx & 15) << 2;
        float4 v;
        if (e0 + e < E) v = csp[idx];
        else            v = make_float4(1.f, 1.f, 1.f, 1.f);
        float ax = frcp_approx(v.x), ay = frcp_approx(v.y);
        float az = frcp_approx(v.z), aw = frcp_approx(v.w);
        float4* dst = (float4*)&s_rcp[e][r4];
        dst[0] = make_float4(ax, ax, ay, ay);
        dst[1] = make_float4(az, az, aw, aw);
    }
    if (tid < ENT) s_xs[tid] = (e0 + tid < E) ? g_xsum[e0 + tid] : 0.f;
    __syncthreads();

    int elim = min(ENT, E - e0);
    for (int ei = 0; ei < elim; ei++) {
        const ulonglong2* rp = (const ulonglong2*)s_rcp[ei];
        u64 acc0 = 0ull, acc1 = 0ull;     // packed (0.f, 0.f)
        #pragma unroll
        for (int rb = 0; rb < 32; rb++) {
            ulonglong2 c = rp[rb];        // LDS.128 broadcast: r=2rb, 2rb+1
            acc0 = ffma2(c.x, w[2 * rb + 0], acc0);
            acc1 = ffma2(c.y, w[2 * rb + 1], acc1);
        }
        u64 acc = fadd2(acc0, acc1);
        float xs = s_xs[ei];
        u64 res = fmul2(acc, pack2(xs, xs));
        *(u64*)(out + (size_t)(e0 + ei) * ODIM + 2 * tid) = res;
    }
}

// ---------------------------------------------------------------------------
extern "C" void kernel_launch(void* const* d_in, const int* in_sizes, int n_in,
                              void* d_out, int out_size) {
    const float* x  = (const float*)d_in[0];
    const float* cs = (const float*)d_in[1];
    const float* W  = (const float*)d_in[2];
    // d_in[3] (edge_index) is mathematically unused by the reference — skipped.
    float* out = (float*)d_out;
    int E = in_sizes[0] / IDIM;

    wsum_kernel<<<RDIM, 1024>>>(W);
    xsum_kernel<<<(E + 7) / 8, 256>>>(x, E);
    rgcn_main_kernel<<<(E + ENT - 1) / ENT, 128>>>(cs, out, E);
}